// round 12
// baseline (speedup 1.0000x reference)
#include <cuda_runtime.h>
#include <cuda_fp16.h>

// Problem: B=4, D=64, K=32, N=8192. Total floats = 2,097,152 = 524288 float4.
#define Kk 32
#define Dk 64
#define TPB 256
#define GRIDA 2048           // encode: 1 float4/thread; blk = bd*8 + chunk
#define GRIDC 1024           // scale:  2 float4/thread; blk = bd*4 + chunk

typedef unsigned long long u64;
typedef unsigned int u32;

__device__ float g_partial[GRIDA];   // per-block sum of E (deterministic)

// ---- fp32 packed helpers ----
__device__ __forceinline__ u64 pk(float lo, float hi) {
    u64 r; asm("mov.b64 %0, {%1,%2};" : "=l"(r) : "f"(lo), "f"(hi)); return r;
}
__device__ __forceinline__ u64 pku(u32 lo, u32 hi) {
    u64 r; asm("mov.b64 %0, {%1,%2};" : "=l"(r) : "r"(lo), "r"(hi)); return r;
}
__device__ __forceinline__ void upk(float& lo, float& hi, u64 v) {
    asm("mov.b64 {%0,%1}, %2;" : "=f"(lo), "=f"(hi) : "l"(v));
}
__device__ __forceinline__ u64 mul2(u64 a, u64 b) {
    u64 r; asm("mul.rn.f32x2 %0, %1, %2;" : "=l"(r) : "l"(a), "l"(b)); return r;
}
__device__ __forceinline__ u64 fma2(u64 a, u64 b, u64 c) {
    u64 r; asm("fma.rn.f32x2 %0, %1, %2, %3;" : "=l"(r) : "l"(a), "l"(b), "l"(c)); return r;
}

// ---- fp16x2 helpers (carried in u32) ----
__device__ __forceinline__ u32 cvt2h(float hi, float lo) {   // {lo, hi}
    u32 r; asm("cvt.rn.f16x2.f32 %0, %1, %2;" : "=r"(r) : "f"(hi), "f"(lo)); return r;
}
__device__ __forceinline__ u32 hex2(u32 a) {                 // 2 exps, 1 MUFU op
    u32 r; asm("ex2.approx.f16x2 %0, %1;" : "=r"(r) : "r"(a)); return r;
}
__device__ __forceinline__ u32 hadd2(u32 a, u32 b) {
    u32 r; asm("add.rn.f16x2 %0, %1, %2;" : "=r"(r) : "r"(a), "r"(b)); return r;
}
__device__ __forceinline__ u32 hfma2(u32 a, u32 b, u32 c) {
    u32 r; asm("fma.rn.f16x2 %0, %1, %2, %3;" : "=r"(r) : "r"(a), "r"(b), "r"(c)); return r;
}
__device__ __forceinline__ float lo2f(u32 h) {
    float f; asm("{.reg .f16 l,h; mov.b32 {l,h}, %1; cvt.f32.f16 %0, l;}" : "=f"(f) : "r"(h)); return f;
}
__device__ __forceinline__ float hi2f(u32 h) {
    float f; asm("{.reg .f16 l,h; mov.b32 {l,h}, %1; cvt.f32.f16 %0, h;}" : "=f"(f) : "r"(h)); return f;
}

// ---- Kernel A: E (unscaled) + per-block partial sums (UNCHANGED from R10) ----
// E[n] = x + (sum_k e_k * (-c_k)) / (sum_k e_k),  e_k = exp2(slx*x^2 + p1*x + p0)
__global__ void __launch_bounds__(TPB)
k_encode(const float* __restrict__ X, const float* __restrict__ cw,
         const float* __restrict__ sc, float* __restrict__ out)
{
    __shared__ uint4 s_cA[Kk];   // (p1,p1,p0,p0) fp32 bits
    __shared__ uint4 s_cB[Kk];   // (sl,sl,hc,hc) fp32,fp32,half2,half2
    __shared__ float s_red[TPB / 32];

    const int t   = threadIdx.x;
    const int blk = blockIdx.x;
    const int d   = (blk >> 3) & 63;

    if (t < Kk) {
        const float c   = cw[t * Dk + d];
        const float slx = sc[t * Dk + d] * 1.4426950408889634f;  // fold log2(e)
        const u32 p1 = __float_as_uint(-2.0f * c * slx);
        const u32 p0 = __float_as_uint(c * c * slx);
        const u32 sl = __float_as_uint(slx);
        const u32 hc = cvt2h(-c, -c);                            // half2(-c,-c)
        s_cA[t] = make_uint4(p1, p1, p0, p0);
        s_cB[t] = make_uint4(sl, sl, hc, hc);
    }
    __syncthreads();

    const float4 v = ((const float4*)X)[blk * TPB + t];
    const u64 xa = pk(v.x, v.y), xb = pk(v.z, v.w);
    const u64 xxa = mul2(xa, xa), xxb = mul2(xb, xb);
    u32 da = 0u, db = 0u, wa = 0u, wb = 0u;     // half2 accumulators

    #pragma unroll 8
    for (int k = 0; k < Kk; k++) {
        const uint4 cA = s_cA[k];               // LDS.128 broadcast
        const uint4 cB = s_cB[k];               // LDS.128 broadcast
        const u64 p1 = pku(cA.x, cA.y), p0 = pku(cA.z, cA.w);
        const u64 sl = pku(cB.x, cB.y);
        const u32 hc = cB.z;
        const u64 a0 = fma2(sl, xxa, fma2(p1, xa, p0));   // fp32 args (<= 0)
        const u64 a1 = fma2(sl, xxb, fma2(p1, xb, p0));
        float l0, h0, l1, h1;
        upk(l0, h0, a0);                        // free (register aliasing)
        upk(l1, h1, a1);
        const u32 e0 = hex2(cvt2h(h0, l0));     // 2 exps per MUFU op
        const u32 e1 = hex2(cvt2h(h1, l1));
        da = hadd2(da, e0);  wa = hfma2(e0, hc, wa);      // w = sum e*(-c)
        db = hadd2(db, e1);  wb = hfma2(e1, hc, wb);
    }

    float4 o;                                   // E = x + w/den
    o.x = v.x + __fdividef(lo2f(wa), lo2f(da));
    o.y = v.y + __fdividef(hi2f(wa), hi2f(da));
    o.z = v.z + __fdividef(lo2f(wb), lo2f(db));
    o.w = v.w + __fdividef(hi2f(wb), hi2f(db));
    ((float4*)out)[blk * TPB + t] = o;          // unscaled E; k_scale rescales

    float ssum = (o.x + o.y) + (o.z + o.w);
    #pragma unroll
    for (int off = 16; off > 0; off >>= 1)
        ssum += __shfl_xor_sync(0xffffffffu, ssum, off);
    if ((t & 31) == 0) s_red[t >> 5] = ssum;
    __syncthreads();
    if (t == 0) {
        float s = 0.f;
        #pragma unroll
        for (int w = 0; w < TPB / 32; w++) s += s_red[w];
        g_partial[blk] = s;
    }
}

// ---- Kernel B: warp-autonomous scale; per-warp gamma, zero block syncs ----
__global__ void __launch_bounds__(TPB)
k_scale(const float* __restrict__ fw, const float* __restrict__ fb,
        float* __restrict__ out)
{
    const int t    = threadIdx.x;
    const int lane = t & 31;
    const int blk  = blockIdx.x;
    const int bd   = blk >> 2;      // 4 blocks per (b,d) plane
    const int d    = bd & 63;
    const int b    = bd >> 6;

    // Issue E loads first; they overlap this warp's gamma chain below.
    float4* base = (float4*)out + blk * 512;
    float4* p0 = base + t;
    float4* p1 = base + TPB + t;
    const float4 e0 = __ldcg(p0);
    const float4 e1 = __ldcg(p1);

    // Per-warp gamma: lane handles j = lane and j = lane+32.
    float acc;
    {
        const int j0 = lane, j1 = lane + 32;
        const float* gp0 = &g_partial[(b * Dk + j0) * 8];
        const float* gp1 = &g_partial[(b * Dk + j1) * 8];
        float s0 = 0.f, s1 = 0.f;
        #pragma unroll
        for (int r = 0; r < 8; r++) s0 += __ldcg(gp0 + r);
        #pragma unroll
        for (int r = 0; r < 8; r++) s1 += __ldcg(gp1 + r);
        acc = s0 * (1.0f / Kk) * __ldg(fw + d * Dk + j0)
            + s1 * (1.0f / Kk) * __ldg(fw + d * Dk + j1);
    }
    #pragma unroll
    for (int off = 16; off > 0; off >>= 1)
        acc += __shfl_xor_sync(0xffffffffu, acc, off);   // all lanes hold dot
    const float g = 1.f + 1.f / (1.f + __expf(-(acc + __ldg(fb + d))));

    float4 o;
    o.x = fmaxf(e0.x * g, 0.f); o.y = fmaxf(e0.y * g, 0.f);
    o.z = fmaxf(e0.z * g, 0.f); o.w = fmaxf(e0.w * g, 0.f);
    *p0 = o;
    o.x = fmaxf(e1.x * g, 0.f); o.y = fmaxf(e1.y * g, 0.f);
    o.z = fmaxf(e1.z * g, 0.f); o.w = fmaxf(e1.w * g, 0.f);
    *p1 = o;
}

extern "C" void kernel_launch(void* const* d_in, const int* in_sizes, int n_in,
                              void* d_out, int out_size)
{
    const float* X   = (const float*)d_in[0];  // (B,D,T,H,W)
    const float* cw  = (const float*)d_in[1];  // (K,D)
    const float* sc  = (const float*)d_in[2];  // (K,D)
    const float* fcw = (const float*)d_in[3];  // (D,D)
    const float* fcb = (const float*)d_in[4];  // (D,)
    float* out = (float*)d_out;

    k_encode<<<GRIDA, TPB>>>(X, cw, sc, out);
    k_scale<<<GRIDC, TPB>>>(fcw, fcb, out);
}

// round 13
// speedup vs baseline: 2.3614x; 2.3614x over previous
#include <cuda_runtime.h>
#include <cuda_fp16.h>

// Problem: B=4, D=64, K=32, N=8192. Total floats = 2,097,152 = 524288 float4.
#define Kk 32
#define Dk 64
#define TPB 256
#define GRID 1024            // both kernels: 2 float4/thread; blk = bd*4 + c4

typedef unsigned long long u64;
typedef unsigned int u32;

// Partials in [b][chunk(4)][d(64)] layout -> warp-coalesced gamma reads.
__device__ float g_partial[1024];

// ---- fp32 packed helpers ----
__device__ __forceinline__ u64 pk(float lo, float hi) {
    u64 r; asm("mov.b64 %0, {%1,%2};" : "=l"(r) : "f"(lo), "f"(hi)); return r;
}
__device__ __forceinline__ u64 pku(u32 lo, u32 hi) {
    u64 r; asm("mov.b64 %0, {%1,%2};" : "=l"(r) : "r"(lo), "r"(hi)); return r;
}
__device__ __forceinline__ void upk(float& lo, float& hi, u64 v) {
    asm("mov.b64 {%0,%1}, %2;" : "=f"(lo), "=f"(hi) : "l"(v));
}
__device__ __forceinline__ u64 mul2(u64 a, u64 b) {
    u64 r; asm("mul.rn.f32x2 %0, %1, %2;" : "=l"(r) : "l"(a), "l"(b)); return r;
}
__device__ __forceinline__ u64 fma2(u64 a, u64 b, u64 c) {
    u64 r; asm("fma.rn.f32x2 %0, %1, %2, %3;" : "=l"(r) : "l"(a), "l"(b), "l"(c)); return r;
}

// ---- fp16x2 helpers (carried in u32) ----
__device__ __forceinline__ u32 cvt2h(float hi, float lo) {   // {lo, hi}
    u32 r; asm("cvt.rn.f16x2.f32 %0, %1, %2;" : "=r"(r) : "f"(hi), "f"(lo)); return r;
}
__device__ __forceinline__ u32 hex2(u32 a) {                 // 2 exps, 1 MUFU op
    u32 r; asm("ex2.approx.f16x2 %0, %1;" : "=r"(r) : "r"(a)); return r;
}
__device__ __forceinline__ u32 hadd2(u32 a, u32 b) {
    u32 r; asm("add.rn.f16x2 %0, %1, %2;" : "=r"(r) : "r"(a), "r"(b)); return r;
}
__device__ __forceinline__ u32 hfma2(u32 a, u32 b, u32 c) {
    u32 r; asm("fma.rn.f16x2 %0, %1, %2, %3;" : "=r"(r) : "r"(a), "r"(b), "r"(c)); return r;
}
__device__ __forceinline__ float lo2f(u32 h) {
    float f; asm("{.reg .f16 l,h; mov.b32 {l,h}, %1; cvt.f32.f16 %0, l;}" : "=f"(f) : "r"(h)); return f;
}
__device__ __forceinline__ float hi2f(u32 h) {
    float f; asm("{.reg .f16 l,h; mov.b32 {l,h}, %1; cvt.f32.f16 %0, h;}" : "=f"(f) : "r"(h)); return f;
}

// ---- Kernel A: E (unscaled) + partials; 2 float4/thread ----
// E[n] = x + (sum_k e_k * (-c_k)) / (sum_k e_k),  e_k = exp2(slx*x^2 + p1*x + p0)
__global__ void __launch_bounds__(TPB)
k_encode(const float* __restrict__ X, const float* __restrict__ cw,
         const float* __restrict__ sc, float* __restrict__ out)
{
    __shared__ uint4 s_cA[Kk];   // (p1,p1,p0,p0) fp32 bits
    __shared__ uint4 s_cB[Kk];   // (sl,sl,hc,hc)
    __shared__ float s_red[TPB / 32];

    const int t   = threadIdx.x;
    const int blk = blockIdx.x;
    const int d   = (blk >> 2) & 63;    // blk = (b*64+d)*4 + c4
    const int b   = blk >> 8;
    const int c4  = blk & 3;

    if (t < Kk) {
        const float c   = cw[t * Dk + d];
        const float slx = sc[t * Dk + d] * 1.4426950408889634f;  // fold log2(e)
        s_cA[t] = make_uint4(__float_as_uint(-2.0f * c * slx),
                             __float_as_uint(-2.0f * c * slx),
                             __float_as_uint(c * c * slx),
                             __float_as_uint(c * c * slx));
        s_cB[t] = make_uint4(__float_as_uint(slx), __float_as_uint(slx),
                             cvt2h(-c, -c), cvt2h(-c, -c));
    }
    __syncthreads();

    const float4 v0 = ((const float4*)X)[blk * 512 + t];
    const float4 v1 = ((const float4*)X)[blk * 512 + TPB + t];
    const u64 x0 = pk(v0.x, v0.y), x1 = pk(v0.z, v0.w);
    const u64 x2 = pk(v1.x, v1.y), x3 = pk(v1.z, v1.w);
    const u64 q0 = mul2(x0, x0), q1 = mul2(x1, x1);
    const u64 q2 = mul2(x2, x2), q3 = mul2(x3, x3);
    u32 d0 = 0u, d1 = 0u, d2 = 0u, d3 = 0u;      // half2 den accumulators
    u32 w0 = 0u, w1 = 0u, w2 = 0u, w3 = 0u;      // half2 w accumulators

    #pragma unroll 8
    for (int k = 0; k < Kk; k++) {
        const uint4 cA = s_cA[k];                // LDS.128 broadcast
        const uint4 cB = s_cB[k];                // LDS.128 broadcast
        const u64 p1 = pku(cA.x, cA.y), p0 = pku(cA.z, cA.w);
        const u64 sl = pku(cB.x, cB.y);
        const u32 hc = cB.z;
        const u64 a0 = fma2(sl, q0, fma2(p1, x0, p0));   // fp32 args (<= 0)
        const u64 a1 = fma2(sl, q1, fma2(p1, x1, p0));
        const u64 a2 = fma2(sl, q2, fma2(p1, x2, p0));
        const u64 a3 = fma2(sl, q3, fma2(p1, x3, p0));
        float f0, f1, f2, f3, f4, f5, f6, f7;
        upk(f0, f1, a0); upk(f2, f3, a1);
        upk(f4, f5, a2); upk(f6, f7, a3);
        const u32 e0 = hex2(cvt2h(f1, f0));      // 2 exps per MUFU op
        const u32 e1 = hex2(cvt2h(f3, f2));
        const u32 e2 = hex2(cvt2h(f5, f4));
        const u32 e3 = hex2(cvt2h(f7, f6));
        d0 = hadd2(d0, e0);  w0 = hfma2(e0, hc, w0);     // w = sum e*(-c)
        d1 = hadd2(d1, e1);  w1 = hfma2(e1, hc, w1);
        d2 = hadd2(d2, e2);  w2 = hfma2(e2, hc, w2);
        d3 = hadd2(d3, e3);  w3 = hfma2(e3, hc, w3);
    }

    float4 o0, o1;                               // E = x + w/den
    o0.x = v0.x + __fdividef(lo2f(w0), lo2f(d0));
    o0.y = v0.y + __fdividef(hi2f(w0), hi2f(d0));
    o0.z = v0.z + __fdividef(lo2f(w1), lo2f(d1));
    o0.w = v0.w + __fdividef(hi2f(w1), hi2f(d1));
    o1.x = v1.x + __fdividef(lo2f(w2), lo2f(d2));
    o1.y = v1.y + __fdividef(hi2f(w2), hi2f(d2));
    o1.z = v1.z + __fdividef(lo2f(w3), lo2f(d3));
    o1.w = v1.w + __fdividef(hi2f(w3), hi2f(d3));
    ((float4*)out)[blk * 512 + t]       = o0;    // unscaled E; k_scale rescales
    ((float4*)out)[blk * 512 + TPB + t] = o1;

    float ssum = ((o0.x + o0.y) + (o0.z + o0.w)) + ((o1.x + o1.y) + (o1.z + o1.w));
    #pragma unroll
    for (int off = 16; off > 0; off >>= 1)
        ssum += __shfl_xor_sync(0xffffffffu, ssum, off);
    if ((t & 31) == 0) s_red[t >> 5] = ssum;
    __syncthreads();
    if (t == 0) {
        float s = 0.f;
        #pragma unroll
        for (int w = 0; w < TPB / 32; w++) s += s_red[w];
        g_partial[b * 256 + c4 * 64 + d] = s;    // [b][chunk][d] layout
    }
}

// ---- Kernel B: warp-autonomous scale; coalesced per-warp gamma, no syncs ----
__global__ void __launch_bounds__(TPB)
k_scale(const float* __restrict__ fw, const float* __restrict__ fb,
        float* __restrict__ out)
{
    const int t    = threadIdx.x;
    const int lane = t & 31;
    const int blk  = blockIdx.x;
    const int d    = (blk >> 2) & 63;
    const int b    = blk >> 8;

    // Issue E loads first; they overlap the gamma chain below.
    float4* p0 = (float4*)out + blk * 512 + t;
    float4* p1 = (float4*)out + blk * 512 + TPB + t;
    const float4 e0 = __ldcg(p0);
    const float4 e1 = __ldcg(p1);

    // Per-warp gamma: 8 coalesced loads/lane over [b][chunk][d] partials.
    // idx = lane + 32*i -> j = idx & 63 = lane (i even) or lane+32 (i odd).
    const float fwa = __ldg(fw + d * Dk + lane);
    const float fwb = __ldg(fw + d * Dk + lane + 32);
    const float* gp = g_partial + b * 256;
    float acc = 0.f;
    #pragma unroll
    for (int i = 0; i < 8; i++) {
        const float p = __ldcg(gp + lane + 32 * i);
        acc = fmaf(p, (i & 1) ? fwb : fwa, acc);
    }
    acc *= (1.0f / Kk);
    #pragma unroll
    for (int off = 16; off > 0; off >>= 1)
        acc += __shfl_xor_sync(0xffffffffu, acc, off);   // all lanes hold dot
    const float g = 1.f + 1.f / (1.f + __expf(-(acc + __ldg(fb + d))));

    float4 o;
    o.x = fmaxf(e0.x * g, 0.f); o.y = fmaxf(e0.y * g, 0.f);
    o.z = fmaxf(e0.z * g, 0.f); o.w = fmaxf(e0.w * g, 0.f);
    *p0 = o;
    o.x = fmaxf(e1.x * g, 0.f); o.y = fmaxf(e1.y * g, 0.f);
    o.z = fmaxf(e1.z * g, 0.f); o.w = fmaxf(e1.w * g, 0.f);
    *p1 = o;
}

extern "C" void kernel_launch(void* const* d_in, const int* in_sizes, int n_in,
                              void* d_out, int out_size)
{
    const float* X   = (const float*)d_in[0];  // (B,D,T,H,W)
    const float* cw  = (const float*)d_in[1];  // (K,D)
    const float* sc  = (const float*)d_in[2];  // (K,D)
    const float* fcw = (const float*)d_in[3];  // (D,D)
    const float* fcb = (const float*)d_in[4];  // (D,)
    float* out = (float*)d_out;

    k_encode<<<GRID, TPB>>>(X, cw, sc, out);
    k_scale<<<GRID, TPB>>>(fcw, fcb, out);
}

// round 14
// speedup vs baseline: 2.6486x; 1.1216x over previous
#include <cuda_runtime.h>
#include <cuda_fp16.h>

// Problem: B=4, D=64, K=32, N=8192. Total floats = 2,097,152 = 524288 float4.
#define Kk 32
#define Dk 64
#define TPB 256
#define GRIDA 1024           // encode: 2 float4/thread; blk = bd*4 + c4
#define GRIDC 512            // scale:  4 float4/thread; blk = bd*2 + c2

typedef unsigned long long u64;
typedef unsigned int u32;

// Partials in [b][chunk(4)][d(64)] layout -> warp-coalesced gamma reads.
__device__ float g_partial[1024];

// ---- fp16x2 helpers (carried in u32) ----
__device__ __forceinline__ u32 cvt2h(float hi, float lo) {   // {lo, hi}
    u32 r; asm("cvt.rn.f16x2.f32 %0, %1, %2;" : "=r"(r) : "f"(hi), "f"(lo)); return r;
}
__device__ __forceinline__ u32 hex2(u32 a) {                 // 2 exps, 1 MUFU op
    u32 r; asm("ex2.approx.f16x2 %0, %1;" : "=r"(r) : "r"(a)); return r;
}
__device__ __forceinline__ u32 hadd2(u32 a, u32 b) {
    u32 r; asm("add.rn.f16x2 %0, %1, %2;" : "=r"(r) : "r"(a), "r"(b)); return r;
}
__device__ __forceinline__ u32 hmul2(u32 a, u32 b) {
    u32 r; asm("mul.rn.f16x2 %0, %1, %2;" : "=r"(r) : "r"(a), "r"(b)); return r;
}
__device__ __forceinline__ u32 hfma2(u32 a, u32 b, u32 c) {
    u32 r; asm("fma.rn.f16x2 %0, %1, %2, %3;" : "=r"(r) : "r"(a), "r"(b), "r"(c)); return r;
}
__device__ __forceinline__ float lo2f(u32 h) {
    float f; asm("{.reg .f16 l,h; mov.b32 {l,h}, %1; cvt.f32.f16 %0, l;}" : "=f"(f) : "r"(h)); return f;
}
__device__ __forceinline__ float hi2f(u32 h) {
    float f; asm("{.reg .f16 l,h; mov.b32 {l,h}, %1; cvt.f32.f16 %0, h;}" : "=f"(f) : "r"(h)); return f;
}

// ---- Kernel A: E (unscaled) + partials; all-half inner loop ----
// e_k = exp2(hsl*x^2 + hp1*x + hp0);  E = x + (sum e*(-c)) / (sum e)
__global__ void __launch_bounds__(TPB)
k_encode(const float* __restrict__ X, const float* __restrict__ cw,
         const float* __restrict__ sc, float* __restrict__ out)
{
    __shared__ uint4 s_c[Kk];    // (hp1, hp0, hsl, hc) as half2 each
    __shared__ float s_red[TPB / 32];

    const int t   = threadIdx.x;
    const int blk = blockIdx.x;
    const int d   = (blk >> 2) & 63;    // blk = (b*64+d)*4 + c4
    const int b   = blk >> 8;
    const int c4  = blk & 3;

    if (t < Kk) {
        const float c   = cw[t * Dk + d];
        const float slx = sc[t * Dk + d] * 1.4426950408889634f;  // fold log2(e)
        const float p1  = -2.0f * c * slx;
        const float p0  = c * c * slx;
        s_c[t] = make_uint4(cvt2h(p1, p1), cvt2h(p0, p0),
                            cvt2h(slx, slx), cvt2h(-c, -c));
    }
    __syncthreads();

    const float4 v0 = ((const float4*)X)[blk * 512 + t];
    const float4 v1 = ((const float4*)X)[blk * 512 + TPB + t];
    // Convert x to half2 ONCE; all k-loop math is fp16x2.
    const u32 hx0 = cvt2h(v0.y, v0.x), hx1 = cvt2h(v0.w, v0.z);
    const u32 hx2 = cvt2h(v1.y, v1.x), hx3 = cvt2h(v1.w, v1.z);
    const u32 hq0 = hmul2(hx0, hx0), hq1 = hmul2(hx1, hx1);
    const u32 hq2 = hmul2(hx2, hx2), hq3 = hmul2(hx3, hx3);
    u32 d0 = 0u, d1 = 0u, d2 = 0u, d3 = 0u;      // half2 den accumulators
    u32 w0 = 0u, w1 = 0u, w2 = 0u, w3 = 0u;      // half2 w accumulators

    #pragma unroll 8
    for (int k = 0; k < Kk; k++) {
        const uint4 cc = s_c[k];                 // ONE LDS.128 per k
        const u32 hp1 = cc.x, hp0 = cc.y, hsl = cc.z, hc = cc.w;
        const u32 a0 = hfma2(hsl, hq0, hfma2(hp1, hx0, hp0));  // arg <= 0
        const u32 a1 = hfma2(hsl, hq1, hfma2(hp1, hx1, hp0));
        const u32 a2 = hfma2(hsl, hq2, hfma2(hp1, hx2, hp0));
        const u32 a3 = hfma2(hsl, hq3, hfma2(hp1, hx3, hp0));
        const u32 e0 = hex2(a0);                 // 2 exps per MUFU op
        const u32 e1 = hex2(a1);
        const u32 e2 = hex2(a2);
        const u32 e3 = hex2(a3);
        d0 = hadd2(d0, e0);  w0 = hfma2(e0, hc, w0);           // w = sum e*(-c)
        d1 = hadd2(d1, e1);  w1 = hfma2(e1, hc, w1);
        d2 = hadd2(d2, e2);  w2 = hfma2(e2, hc, w2);
        d3 = hadd2(d3, e3);  w3 = hfma2(e3, hc, w3);
    }

    float4 o0, o1;                               // E = x + w/den (fp32 finish)
    o0.x = v0.x + __fdividef(lo2f(w0), lo2f(d0));
    o0.y = v0.y + __fdividef(hi2f(w0), hi2f(d0));
    o0.z = v0.z + __fdividef(lo2f(w1), lo2f(d1));
    o0.w = v0.w + __fdividef(hi2f(w1), hi2f(d1));
    o1.x = v1.x + __fdividef(lo2f(w2), lo2f(d2));
    o1.y = v1.y + __fdividef(hi2f(w2), hi2f(d2));
    o1.z = v1.z + __fdividef(lo2f(w3), lo2f(d3));
    o1.w = v1.w + __fdividef(hi2f(w3), hi2f(d3));
    ((float4*)out)[blk * 512 + t]       = o0;    // unscaled E; k_scale rescales
    ((float4*)out)[blk * 512 + TPB + t] = o1;

    float ssum = ((o0.x + o0.y) + (o0.z + o0.w)) + ((o1.x + o1.y) + (o1.z + o1.w));
    #pragma unroll
    for (int off = 16; off > 0; off >>= 1)
        ssum += __shfl_xor_sync(0xffffffffu, ssum, off);
    if ((t & 31) == 0) s_red[t >> 5] = ssum;
    __syncthreads();
    if (t == 0) {
        float s = 0.f;
        #pragma unroll
        for (int w = 0; w < TPB / 32; w++) s += s_red[w];
        g_partial[b * 256 + c4 * 64 + d] = s;    // [b][chunk][d] layout
    }
}

// ---- Kernel B: warp-autonomous scale; 4 float4/thread, coalesced gamma ----
__global__ void __launch_bounds__(TPB)
k_scale(const float* __restrict__ fw, const float* __restrict__ fb,
        float* __restrict__ out)
{
    const int t    = threadIdx.x;
    const int lane = t & 31;
    const int blk  = blockIdx.x;
    const int d    = (blk >> 1) & 63;   // blk = (b*64+d)*2 + c2
    const int b    = blk >> 7;

    // Issue ALL 4 E loads first; they overlap the gamma chain below.
    float4* base = (float4*)out + blk * 1024;
    float4 e[4];
    #pragma unroll
    for (int i = 0; i < 4; i++) e[i] = __ldcg(base + i * TPB + t);

    // Per-warp gamma: 8 coalesced loads/lane over [b][chunk][d] partials.
    // idx = lane + 32*i -> j = idx & 63 = lane (i even) or lane+32 (i odd).
    const float fwa = __ldg(fw + d * Dk + lane);
    const float fwb = __ldg(fw + d * Dk + lane + 32);
    const float* gp = g_partial + b * 256;
    float acc = 0.f;
    #pragma unroll
    for (int i = 0; i < 8; i++) {
        const float p = __ldcg(gp + lane + 32 * i);
        acc = fmaf(p, (i & 1) ? fwb : fwa, acc);
    }
    acc *= (1.0f / Kk);
    #pragma unroll
    for (int off = 16; off > 0; off >>= 1)
        acc += __shfl_xor_sync(0xffffffffu, acc, off);   // all lanes hold dot
    const float g = 1.f + 1.f / (1.f + __expf(-(acc + __ldg(fb + d))));

    #pragma unroll
    for (int i = 0; i < 4; i++) {
        float4 o;
        o.x = fmaxf(e[i].x * g, 0.f); o.y = fmaxf(e[i].y * g, 0.f);
        o.z = fmaxf(e[i].z * g, 0.f); o.w = fmaxf(e[i].w * g, 0.f);
        base[i * TPB + t] = o;
    }
}

extern "C" void kernel_launch(void* const* d_in, const int* in_sizes, int n_in,
                              void* d_out, int out_size)
{
    const float* X   = (const float*)d_in[0];  // (B,D,T,H,W)
    const float* cw  = (const float*)d_in[1];  // (K,D)
    const float* sc  = (const float*)d_in[2];  // (K,D)
    const float* fcw = (const float*)d_in[3];  // (D,D)
    const float* fcb = (const float*)d_in[4];  // (D,)
    float* out = (float*)d_out;

    k_encode<<<GRIDA, TPB>>>(X, cw, sc, out);
    k_scale<<<GRIDC, TPB>>>(fcw, fcb, out);
}

// round 15
// speedup vs baseline: 2.6531x; 1.0017x over previous
#include <cuda_runtime.h>
#include <cuda_fp16.h>

// Problem: B=4, D=64, K=32, N=8192. Total floats = 2,097,152 = 524288 float4.
#define Kk 32
#define Dk 64
#define GRIDA 512            // encode: TPB 256, 4 float4/thread; blk = bd*2 + c2
#define GRIDC 1024           // scale:  TPB 128, 4 float4/thread; blk = bd*4 + c4

typedef unsigned int u32;

// Partials in [b][chunk(2)][d(64)] layout -> warp-coalesced gamma reads.
__device__ float g_partial[512];

// ---- fp16x2 helpers (carried in u32) ----
__device__ __forceinline__ u32 cvt2h(float hi, float lo) {   // {lo, hi}
    u32 r; asm("cvt.rn.f16x2.f32 %0, %1, %2;" : "=r"(r) : "f"(hi), "f"(lo)); return r;
}
__device__ __forceinline__ u32 hex2(u32 a) {                 // 2 exps, 1 MUFU op
    u32 r; asm("ex2.approx.f16x2 %0, %1;" : "=r"(r) : "r"(a)); return r;
}
__device__ __forceinline__ u32 hadd2(u32 a, u32 b) {
    u32 r; asm("add.rn.f16x2 %0, %1, %2;" : "=r"(r) : "r"(a), "r"(b)); return r;
}
__device__ __forceinline__ u32 hmul2(u32 a, u32 b) {
    u32 r; asm("mul.rn.f16x2 %0, %1, %2;" : "=r"(r) : "r"(a), "r"(b)); return r;
}
__device__ __forceinline__ u32 hfma2(u32 a, u32 b, u32 c) {
    u32 r; asm("fma.rn.f16x2 %0, %1, %2, %3;" : "=r"(r) : "r"(a), "r"(b), "r"(c)); return r;
}
__device__ __forceinline__ float lo2f(u32 h) {
    float f; asm("{.reg .f16 l,h; mov.b32 {l,h}, %1; cvt.f32.f16 %0, l;}" : "=f"(f) : "r"(h)); return f;
}
__device__ __forceinline__ float hi2f(u32 h) {
    float f; asm("{.reg .f16 l,h; mov.b32 {l,h}, %1; cvt.f32.f16 %0, h;}" : "=f"(f) : "r"(h)); return f;
}

// ---- Kernel A: E (unscaled) + partials; all-half loop, 4 float4/thread ----
// e_k = exp2(hsl*x^2 + hp1*x + hp0);  E = x + (sum e*(-c)) / (sum e)
__global__ void __launch_bounds__(256)
k_encode(const float* __restrict__ X, const float* __restrict__ cw,
         const float* __restrict__ sc, float* __restrict__ out)
{
    __shared__ uint4 s_c[Kk];    // (hp1, hp0, hsl, hc) as half2 each
    __shared__ float s_red[8];

    const int t   = threadIdx.x;
    const int blk = blockIdx.x;
    const int d   = (blk >> 1) & 63;    // blk = (b*64+d)*2 + c2
    const int b   = blk >> 7;
    const int c2  = blk & 1;

    if (t < Kk) {
        const float c   = cw[t * Dk + d];
        const float slx = sc[t * Dk + d] * 1.4426950408889634f;  // fold log2(e)
        const float p1  = -2.0f * c * slx;
        const float p0  = c * c * slx;
        s_c[t] = make_uint4(cvt2h(p1, p1), cvt2h(p0, p0),
                            cvt2h(slx, slx), cvt2h(-c, -c));
    }
    __syncthreads();

    float4 v[4];
    #pragma unroll
    for (int i = 0; i < 4; i++) v[i] = ((const float4*)X)[blk * 1024 + i * 256 + t];

    u32 hx[8], hq[8], dn[8], w[8];
    #pragma unroll
    for (int i = 0; i < 4; i++) {
        hx[i * 2 + 0] = cvt2h(v[i].y, v[i].x);
        hx[i * 2 + 1] = cvt2h(v[i].w, v[i].z);
    }
    #pragma unroll
    for (int p = 0; p < 8; p++) {
        hq[p] = hmul2(hx[p], hx[p]);
        dn[p] = 0u;  w[p] = 0u;
    }

    #pragma unroll 4
    for (int k = 0; k < Kk; k++) {
        const uint4 cc = s_c[k];                 // ONE LDS.128 per k (16 elems)
        const u32 hp1 = cc.x, hp0 = cc.y, hsl = cc.z, hc = cc.w;
        #pragma unroll
        for (int p = 0; p < 8; p++) {
            const u32 a = hfma2(hsl, hq[p], hfma2(hp1, hx[p], hp0));  // arg <= 0
            const u32 e = hex2(a);               // 2 exps per MUFU op
            dn[p] = hadd2(dn[p], e);
            w[p]  = hfma2(e, hc, w[p]);          // w = sum e*(-c)
        }
    }

    float ssum = 0.f;
    #pragma unroll
    for (int i = 0; i < 4; i++) {
        float4 o;                                // E = x + w/den (fp32 finish)
        o.x = v[i].x + __fdividef(lo2f(w[i*2]),   lo2f(dn[i*2]));
        o.y = v[i].y + __fdividef(hi2f(w[i*2]),   hi2f(dn[i*2]));
        o.z = v[i].z + __fdividef(lo2f(w[i*2+1]), lo2f(dn[i*2+1]));
        o.w = v[i].w + __fdividef(hi2f(w[i*2+1]), hi2f(dn[i*2+1]));
        ((float4*)out)[blk * 1024 + i * 256 + t] = o;   // unscaled E
        ssum += ((o.x + o.y) + (o.z + o.w));
    }

    #pragma unroll
    for (int off = 16; off > 0; off >>= 1)
        ssum += __shfl_xor_sync(0xffffffffu, ssum, off);
    if ((t & 31) == 0) s_red[t >> 5] = ssum;
    __syncthreads();
    if (t == 0) {
        float s = 0.f;
        #pragma unroll
        for (int wv = 0; wv < 8; wv++) s += s_red[wv];
        g_partial[b * 128 + c2 * 64 + d] = s;    // [b][chunk][d] layout
    }
}

// ---- Kernel B: warp-autonomous scale; TPB 128, 4 float4/thread ----
__global__ void __launch_bounds__(128)
k_scale(const float* __restrict__ fw, const float* __restrict__ fb,
        float* __restrict__ out)
{
    const int t    = threadIdx.x;
    const int lane = t & 31;
    const int blk  = blockIdx.x;
    const int d    = (blk >> 2) & 63;   // blk = (b*64+d)*4 + c4
    const int b    = blk >> 8;

    // Issue ALL 4 E loads first; they overlap the gamma chain below.
    float4* base = (float4*)out + blk * 512;
    float4 e[4];
    #pragma unroll
    for (int i = 0; i < 4; i++) e[i] = __ldcg(base + i * 128 + t);

    // Per-warp gamma: 4 coalesced loads/lane over [b][chunk(2)][d] partials.
    // idx = lane + 32*i -> j = idx & 63 = lane (i even) or lane+32 (i odd).
    const float fwa = __ldg(fw + d * Dk + lane);
    const float fwb = __ldg(fw + d * Dk + lane + 32);
    const float* gp = g_partial + b * 128;
    float acc = 0.f;
    #pragma unroll
    for (int i = 0; i < 4; i++) {
        const float p = __ldcg(gp + lane + 32 * i);
        acc = fmaf(p, (i & 1) ? fwb : fwa, acc);
    }
    acc *= (1.0f / Kk);
    #pragma unroll
    for (int off = 16; off > 0; off >>= 1)
        acc += __shfl_xor_sync(0xffffffffu, acc, off);   // all lanes hold dot
    const float g = 1.f + 1.f / (1.f + __expf(-(acc + __ldg(fb + d))));

    #pragma unroll
    for (int i = 0; i < 4; i++) {
        float4 o;
        o.x = fmaxf(e[i].x * g, 0.f); o.y = fmaxf(e[i].y * g, 0.f);
        o.z = fmaxf(e[i].z * g, 0.f); o.w = fmaxf(e[i].w * g, 0.f);
        base[i * 128 + t] = o;
    }
}

extern "C" void kernel_launch(void* const* d_in, const int* in_sizes, int n_in,
                              void* d_out, int out_size)
{
    const float* X   = (const float*)d_in[0];  // (B,D,T,H,W)
    const float* cw  = (const float*)d_in[1];  // (K,D)
    const float* sc  = (const float*)d_in[2];  // (K,D)
    const float* fcw = (const float*)d_in[3];  // (D,D)
    const float* fcb = (const float*)d_in[4];  // (D,)
    float* out = (float*)d_out;

    k_encode<<<GRIDA, 256>>>(X, cw, sc, out);
    k_scale<<<GRIDC, 128>>>(fcw, fcb, out);
}